// round 16
// baseline (speedup 1.0000x reference)
#include <cuda_runtime.h>
#include <cuda_fp16.h>
#include <cstdint>

typedef __half fp16;

#define STAGE_BYTES 49152               // A 128x128B (16K) + B 256x128B (32K)
#define NSTAGE 4
#define SMEM_ALLOC (1024 + NSTAGE*STAGE_BYTES)

#define BIG 8388608ULL
#define MB1 1048576ULL

// fp16 arena: FIN 0-3, FP 3-6, Q 6-9, K 9-12, VT 12-15, QS1 15, P 16-19, W 19..+12MB1
__device__ fp16  g_hf[19ULL*BIG + 12ULL*MB1];
// f32 arena: S 0-3, T 3-4, Qf2 4-5, Qf3 5-6
__device__ float g_f[6ULL*BIG];

__device__ __forceinline__ uint32_t su32(const void* p){ return (uint32_t)__cvta_generic_to_shared(p); }
__device__ __forceinline__ void cp16(uint32_t s, const void* g){
    asm volatile("cp.async.cg.shared.global [%0], [%1], 16;"
        :: "r"(s), "l"((unsigned long long)__cvta_generic_to_global(g)) : "memory");
}
__device__ __forceinline__ uint32_t pk(fp16 a, fp16 b){
    return (uint32_t)__half_as_ushort(a) | ((uint32_t)__half_as_ushort(b) << 16);
}
__device__ __forceinline__ uint32_t swz(uint32_t o){ return o ^ ((o >> 3) & 0x70); }

__device__ __forceinline__ void mbar_init(uint32_t a, uint32_t n){
    asm volatile("mbarrier.init.shared.b64 [%0], %1;" :: "r"(a), "r"(n) : "memory");
}
__device__ __forceinline__ void mbar_arrive(uint32_t a){
    asm volatile("mbarrier.arrive.shared.b64 _, [%0];" :: "r"(a) : "memory");
}
__device__ __forceinline__ void cpasync_mbar_arrive_noinc(uint32_t a){
    asm volatile("cp.async.mbarrier.arrive.noinc.shared.b64 [%0];" :: "r"(a) : "memory");
}
__device__ __forceinline__ void mbar_wait(uint32_t a, uint32_t ph){
    asm volatile("{\n\t.reg .pred P;\n\t"
        "WL_%=:\n\t"
        "mbarrier.try_wait.parity.acquire.cta.shared::cta.b64 P, [%0], %1, 0x989680;\n\t"
        "@P bra.uni WD_%=;\n\t"
        "bra.uni WL_%=;\n\t"
        "WD_%=:\n\t}" :: "r"(a), "r"(ph) : "memory");
}

__device__ __forceinline__ void ldsm4(uint32_t* r, uint32_t addr){
    asm volatile("ldmatrix.sync.aligned.m8n8.x4.shared.b16 {%0,%1,%2,%3}, [%4];"
        : "=r"(r[0]), "=r"(r[1]), "=r"(r[2]), "=r"(r[3]) : "r"(addr));
}
__device__ __forceinline__ void mma16816(float* d, const uint32_t* a, const uint32_t* b){
    asm volatile("mma.sync.aligned.m16n8k16.row.col.f32.f16.f16.f32 "
        "{%0,%1,%2,%3}, {%4,%5,%6,%7}, {%8,%9}, {%0,%1,%2,%3};"
        : "+f"(d[0]), "+f"(d[1]), "+f"(d[2]), "+f"(d[3])
        : "r"(a[0]), "r"(a[1]), "r"(a[2]), "r"(a[3]), "r"(b[0]), "r"(b[1]));
}

struct GDesc {
    const fp16 *Ah, *Bh;
    long long sA, sB;
    const float* bias;
    const float* AccC; long long sAcc;
    float* Cf; long long sCf; int ldcf;
    fp16 *Chi;
    int trans, relu, wf32, wsplit;
};
struct GTable { GDesc d[9]; int nb; };

__device__ __forceinline__ void ldfrA(uint32_t (*afb)[4], uint32_t sa, int kb,
                                      int wm, int r8, int sg)
{
#pragma unroll
    for (int mt = 0; mt < 4; mt++) {
        int row = wm + mt*16 + r8 + ((sg & 1) << 3);
        ldsm4(afb[mt], sa + swz((uint32_t)(row*128 + kb + ((sg >> 1) << 4))));
    }
}
__device__ __forceinline__ void ldfrB(uint32_t (*bfb)[4], uint32_t sb, int kb,
                                      int wn, int r8, int sg)
{
#pragma unroll
    for (int nq = 0; nq < 4; nq++) {
        int row = wn + nq*16 + r8 + ((sg >> 1) << 3);
        ldsm4(bfb[nq], sb + swz((uint32_t)(row*128 + kb + ((sg & 1) << 4))));
    }
}

// batched fp16 GEMM: C[128x256 tile] = A B^T (+AccC) (+bias,relu)
// 256 thr, 8 warps (2M x 4N), warp tile 64x64; 4-stage mbarrier pipeline, depth 2
__global__ void __launch_bounds__(256, 1) gemm_b(GTable t)
{
    extern __shared__ char smem[];
    const uint32_t sbase = su32(smem);
    const uint32_t tbase = (sbase + 1023u) & ~1023u;
    const int tid = threadIdx.x, wid = tid >> 5, lane = tid & 31;
    const int di = blockIdx.z / t.nb, zb = blockIdx.z - di * t.nb;
    const GDesc g = t.d[di];
    const int m0 = blockIdx.y * 128, n0 = blockIdx.x * 256;
    const int wm = (wid & 1) * 64, wn = (wid >> 1) * 64;
    const int r8 = lane & 7, sg = lane >> 3;

    // mbarriers: full[s] at sbase+16*s, empty[s] at sbase+16*s+8
    if (tid == 0) {
#pragma unroll
        for (int s = 0; s < NSTAGE; s++) {
            mbar_init(sbase + 16*s, 256);       // full: 256 deferred cp.async arrivals
            mbar_init(sbase + 16*s + 8, 256);   // empty: 256 thread arrivals
        }
    }
    __syncthreads();

    const fp16* Ah = g.Ah + (long long)zb * g.sA;
    const fp16* Bh = g.Bh + (long long)zb * g.sB;

    float acc[4][8][4];
#pragma unroll
    for (int a = 0; a < 4; a++)
#pragma unroll
        for (int b = 0; b < 8; b++)
#pragma unroll
            for (int c = 0; c < 4; c++) acc[a][b][c] = 0.f;

    auto produce = [&](int j) {
        const int slot = j & 3;
        if (j >= NSTAGE) mbar_wait(sbase + 16*slot + 8, ((uint32_t)(j >> 2) - 1u) & 1u);
        const int k0 = j * 64;
        const uint32_t sa = tbase + (uint32_t)slot * STAGE_BYTES;
        const uint32_t sb = sa + 16384;
#pragma unroll
        for (int u = 0; u < 4; u++) {            // A: 128x64
            int s = tid + 256 * u, row = s >> 3, cs = s & 7;
            uint32_t so = swz((uint32_t)(row * 128 + cs * 16));
            cp16(sa + so, Ah + (size_t)(m0 + row) * 1024 + k0 + cs * 8);
        }
#pragma unroll
        for (int u = 0; u < 8; u++) {            // B: 256x64
            int s = tid + 256 * u, row = s >> 3, cs = s & 7;
            uint32_t so = swz((uint32_t)(row * 128 + cs * 16));
            cp16(sb + so, Bh + (size_t)(n0 + row) * 1024 + k0 + cs * 8);
        }
        cpasync_mbar_arrive_noinc(sbase + 16*slot);
    };

    produce(0);
    produce(1);

    uint32_t af[2][4][4], bfr[2][4][4];

#pragma unroll 1
    for (int i = 0; i < 16; i++) {
        if (i + 2 < 16) produce(i + 2);
        const int slot = i & 3;
        mbar_wait(sbase + 16*slot, (uint32_t)(i >> 2) & 1u);

        const uint32_t sa = tbase + (uint32_t)slot * STAGE_BYTES;
        const uint32_t sb = sa + 16384;

        ldfrA(af[0], sa, 0, wm, r8, sg);
        ldfrB(bfr[0], sb, 0, wn, r8, sg);
#pragma unroll
        for (int ks = 0; ks < 4; ks++) {
            const int cur = ks & 1;
            if (ks < 3) {
                ldfrA(af[cur ^ 1], sa, (ks + 1) * 32, wm, r8, sg);
                ldfrB(bfr[cur ^ 1], sb, (ks + 1) * 32, wn, r8, sg);
            }
#pragma unroll
            for (int mt = 0; mt < 4; mt++)
#pragma unroll
                for (int nq = 0; nq < 4; nq++) {
                    mma16816(acc[mt][2*nq],     af[cur][mt], bfr[cur][nq]);
                    mma16816(acc[mt][2*nq + 1], af[cur][mt], bfr[cur][nq] + 2);
                }
        }
        mbar_arrive(sbase + 16*slot + 8);
    }

#pragma unroll
    for (int mt = 0; mt < 4; mt++)
#pragma unroll
        for (int ri = 0; ri < 2; ri++) {
            const long long rg = m0 + wm + mt * 16 + ri * 8 + (lane >> 2);
            const float* accp = g.AccC ? g.AccC + (long long)zb * g.sAcc + rg * 1024 : nullptr;
            float* cf = g.wf32 ? g.Cf + (long long)zb * g.sCf + rg * (long long)g.ldcf : nullptr;
            fp16 *chi = nullptr;
            long long bb = 0, tb = 0;
            if (g.wsplit) {
                if (g.trans) { bb = (rg >> 10) * 1048576LL; tb = rg & 1023LL; }
                else         { chi = g.Chi + rg * 1024LL; }
            }
#pragma unroll
            for (int nt = 0; nt < 8; nt++) {
                const int c = n0 + wn + nt * 8 + (lane & 3) * 2;
                float v0 = acc[mt][nt][ri * 2];
                float v1 = acc[mt][nt][ri * 2 + 1];
                if (accp) { float2 tv = *(const float2*)(accp + c); v0 += tv.x; v1 += tv.y; }
                if (g.relu) {
                    v0 = fmaxf(v0 + g.bias[c], 0.f);
                    v1 = fmaxf(v1 + g.bias[c + 1], 0.f);
                }
                if (cf) *(float2*)(cf + c) = make_float2(v0, v1);
                if (g.wsplit) {
                    fp16 h0 = __float2half_rn(v0), h1 = __float2half_rn(v1);
                    if (g.trans) {
                        g.Chi[bb + (long long)c * 1024 + tb] = h0;
                        g.Chi[bb + (long long)(c + 1) * 1024 + tb] = h1;
                    } else {
                        *(uint32_t*)(chi + c) = pk(h0, h1);
                    }
                }
            }
        }
}

// input convert: fp16
__global__ void cvt_in_k(const float* f0, const float* f1, const float* f2, fp16* base)
{
    const float* src = (blockIdx.y == 0) ? f0 : (blockIdx.y == 1) ? f1 : f2;
    size_t i = (size_t)blockIdx.x * 256 + threadIdx.x;
    float4 v = ((const float4*)src)[i];
    uint2 h = make_uint2(pk(__float2half_rn(v.x), __float2half_rn(v.y)),
                         pk(__float2half_rn(v.z), __float2half_rn(v.w)));
    ((uint2*)(base + (size_t)blockIdx.y*BIG))[i] = h;
}

struct WPtrs { const float* p[12]; };
__global__ void cvt_w_k(WPtrs w, fp16* wb)
{
    size_t i = (size_t)blockIdx.x * 256 + threadIdx.x;
    float4 v = ((const float4*)w.p[blockIdx.y])[i];
    uint2 h = make_uint2(pk(__float2half_rn(v.x), __float2half_rn(v.y)),
                         pk(__float2half_rn(v.z), __float2half_rn(v.w)));
    ((uint2*)(wb + (size_t)blockIdx.y*MB1))[i] = h;
}

__global__ void add_h_k(const float* __restrict__ a, const float* __restrict__ b,
                        fp16* __restrict__ hi)
{
    size_t i = (size_t)blockIdx.x * 256 + threadIdx.x;
    float4 x = ((const float4*)a)[i];
    float4 y = ((const float4*)b)[i];
    x.x += y.x; x.y += y.y; x.z += y.z; x.w += y.w;
    uint2 h = make_uint2(pk(__float2half_rn(x.x), __float2half_rn(x.y)),
                         pk(__float2half_rn(x.z), __float2half_rn(x.w)));
    ((uint2*)hi)[i] = h;
}

// softmax over rows of 1024; grid.x = 3*8192; P fp16
__global__ void softmax3_k(const float* __restrict__ S, fp16* __restrict__ P)
{
    __shared__ float red[256];
    const int m = blockIdx.x >> 13;
    const size_t row = blockIdx.x & 8191;
    const float* p = S + (size_t)m * BIG + row * 1024;
    int tid = threadIdx.x;
    float4 v = ((const float4*)p)[tid];
    float mx = fmaxf(fmaxf(v.x, v.y), fmaxf(v.z, v.w));
    red[tid] = mx; __syncthreads();
    for (int s = 128; s > 0; s >>= 1) { if (tid < s) red[tid] = fmaxf(red[tid], red[tid+s]); __syncthreads(); }
    mx = red[0]; __syncthreads();
    v.x = __expf(v.x-mx); v.y = __expf(v.y-mx); v.z = __expf(v.z-mx); v.w = __expf(v.w-mx);
    red[tid] = v.x + v.y + v.z + v.w; __syncthreads();
    for (int s = 128; s > 0; s >>= 1) { if (tid < s) red[tid] += red[tid+s]; __syncthreads(); }
    float inv = 1.f / red[0];
    v.x *= inv; v.y *= inv; v.z *= inv; v.w *= inv;
    uint2 h = make_uint2(pk(__float2half_rn(v.x), __float2half_rn(v.y)),
                         pk(__float2half_rn(v.z), __float2half_rn(v.w)));
    ((uint2*)(P + (size_t)m*BIG))[row * 256 + tid] = h;
}

extern "C" void kernel_launch(void* const* d_in, const int* in_sizes, int n_in,
                              void* d_out, int out_size)
{
    const float* f[3]  = { (const float*)d_in[0], (const float*)d_in[1], (const float*)d_in[2] };
    const float* W[12]; for (int j = 0; j < 12; j++) W[j] = (const float*)d_in[3 + j];
    const float* bp[3] = { (const float*)d_in[15], (const float*)d_in[16], (const float*)d_in[17] };
    float* out = (float*)d_out;

    fp16* HF = nullptr;  cudaGetSymbolAddress((void**)&HF, g_hf);
    float* F32 = nullptr; cudaGetSymbolAddress((void**)&F32, g_f);

    fp16 *FIN = HF, *FP = HF + 3*BIG, *Qh = HF + 6*BIG;
    fp16 *Kb = HF + 9*BIG, *VT = HF + 12*BIG;
    fp16 *QS1 = HF + 15*BIG, *P = HF + 16*BIG, *Wb = HF + 19*BIG;
    float *S = F32, *T = F32 + 3*BIG, *Qf2 = F32 + 4*BIG, *Qf3 = F32 + 5*BIG;

    cudaFuncSetAttribute(gemm_b, cudaFuncAttributeMaxDynamicSharedMemorySize, SMEM_ALLOC);

    cvt_in_k<<<dim3(8192,3), 256>>>(f[0], f[1], f[2], FIN);
    WPtrs wp; for (int j = 0; j < 12; j++) wp.p[j] = W[j];
    cvt_w_k<<<dim3(1024,12), 256>>>(wp, Wb);

    // 1) preprocess: fp_i = relu(f_i Wp_i^T + b_i) -> out + FP fp16
    {
        GTable t = {}; t.nb = 1;
        for (int i = 0; i < 3; i++) {
            GDesc& d = t.d[i];
            d.Ah = FIN + (size_t)i*BIG; d.Bh = Wb + (size_t)i*MB1;
            d.bias = bp[i]; d.relu = 1;
            d.wf32 = 1; d.Cf = out + 3072 + i*1024; d.ldcf = 6144; d.sCf = 0;
            d.wsplit = 1; d.Chi = FP + (size_t)i*BIG;
        }
        gemm_b<<<dim3(4,64,3), 256, SMEM_ALLOC>>>(t);
    }
    // 2) QKV: Q fp16 (+fp32 for i=1,2), K fp16, V fp16 transposed
    {
        GTable t = {}; t.nb = 1;
        for (int i = 0; i < 3; i++) {
            GDesc* d = &t.d[3*i];
            d[0].Ah = d[1].Ah = d[2].Ah = FP + (size_t)i*BIG;
            d[0].Bh = Wb + (size_t)(3+3*i)*MB1;
            d[1].Bh = Wb + (size_t)(4+3*i)*MB1;
            d[2].Bh = Wb + (size_t)(5+3*i)*MB1;
            d[0].wsplit = 1; d[0].Chi = Qh + (size_t)i*BIG;
            d[1].wsplit = 1; d[1].Chi = Kb + (size_t)i*BIG;
            d[2].wsplit = 1; d[2].Chi = VT + (size_t)i*BIG; d[2].trans = 1;
            if (i == 1) { d[0].wf32 = 1; d[0].Cf = Qf2; d[0].ldcf = 1024; }
            if (i == 2) { d[0].wf32 = 1; d[0].Cf = Qf3; d[0].ldcf = 1024; }
        }
        gemm_b<<<dim3(4,64,9), 256, SMEM_ALLOC>>>(t);
    }
    // 3) qs1 = fp16(q2 + q3)
    add_h_k<<<8192, 256>>>(Qf2, Qf3, QS1);

    // 4) T = q1 . k3^T (fp32)
    {
        GTable t = {}; t.nb = 8;
        GDesc& d = t.d[0];
        d.Ah = Qh; d.Bh = Kb + 2*BIG;
        d.sA = 1048576; d.sB = 1048576;
        d.wf32 = 1; d.Cf = T; d.ldcf = 1024; d.sCf = 1048576;
        gemm_b<<<dim3(4,8,8), 256, SMEM_ALLOC>>>(t);
    }
    // 5) scores: s1 = qs1.k1 ; s2 = T + q3.k2 ; s3 = T + q2.k3
    {
        GTable t = {}; t.nb = 8;
        const fp16* ah[3] = { QS1, Qh + 2*BIG, Qh + 1*BIG };
        const int ki[3] = { 0, 1, 2 };
        for (int m = 0; m < 3; m++) {
            GDesc& d = t.d[m];
            d.Ah = ah[m]; d.Bh = Kb + (size_t)ki[m]*BIG;
            d.sA = 1048576; d.sB = 1048576;
            if (m > 0) { d.AccC = T; d.sAcc = 1048576; }
            d.wf32 = 1; d.Cf = S + (size_t)m*BIG; d.ldcf = 1024; d.sCf = 1048576;
        }
        gemm_b<<<dim3(4,8,24), 256, SMEM_ALLOC>>>(t);
    }
    // 6) softmax -> P fp16
    softmax3_k<<<24576, 256>>>(S, P);

    // 7) AV: f_mu = P_m @ V_m -> out cols [m*1024, (m+1)*1024)
    {
        GTable t = {}; t.nb = 8;
        for (int m = 0; m < 3; m++) {
            GDesc& d = t.d[m];
            d.Ah = P + (size_t)m*BIG; d.Bh = VT + (size_t)m*BIG;
            d.sA = 1048576; d.sB = 1048576;
            d.wf32 = 1; d.Cf = out + m*1024; d.ldcf = 6144; d.sCf = (long long)1024*6144;
        }
        gemm_b<<<dim3(4,8,24), 256, SMEM_ALLOC>>>(t);
    }
}